// round 3
// baseline (speedup 1.0000x reference)
#include <cuda_runtime.h>

#define NDIM 2304   // 48*48 tokens
#define CDIM 256
#define HEADS 8
#define HD 32

// scratch (no allocs allowed)
__device__ float g_q[CDIM * NDIM];
__device__ float g_k[CDIM * NDIM];
__device__ float g_v[CDIM * NDIM];
__device__ float g_o[CDIM * NDIM];

union U64 { unsigned long long u; float2 f; };

__device__ __forceinline__ void ffma2(unsigned long long& acc,
                                      unsigned long long a,
                                      unsigned long long b) {
    asm("fma.rn.f32x2 %0, %1, %2, %0;" : "+l"(acc) : "l"(a), "l"(b));
}

// ---------------------------------------------------------------------------
// GEMM: Y[o][n] = sum_c W[o][c] * X[c][n] + b[o];  M=256, K=256, N=2304
// 64x64 tile per CTA, 256 threads, 4x4 per thread, f32x2 packed FMA.
// ---------------------------------------------------------------------------
__device__ __forceinline__ void gemm_tile(const float* __restrict__ W,
                                          const float* __restrict__ bias,
                                          const float* __restrict__ X,
                                          float* __restrict__ Y) {
    __shared__ float2 wsd[16 * 64];  // [k][o], value duplicated {w,w}
    __shared__ float  xs [16 * 64];  // [k][n]

    const int tid = threadIdx.x;
    const int n0 = blockIdx.x * 64;
    const int o0 = blockIdx.y * 64;
    const int i0 = (tid >> 4) * 4;   // output row group
    const int j0 = (tid & 15) * 4;   // output col group

    U64 acc[4][2];
#pragma unroll
    for (int a = 0; a < 4; a++) { acc[a][0].u = 0ull; acc[a][1].u = 0ull; }

    const int ow = tid >> 2;
    const int kc = (tid & 3) * 4;
    const int xr = tid >> 6;
    const int xc = tid & 63;

    for (int k0 = 0; k0 < 256; k0 += 16) {
        __syncthreads();
        float4 w4 = *(const float4*)(W + (o0 + ow) * 256 + k0 + kc);
        wsd[(kc + 0) * 64 + ow] = make_float2(w4.x, w4.x);
        wsd[(kc + 1) * 64 + ow] = make_float2(w4.y, w4.y);
        wsd[(kc + 2) * 64 + ow] = make_float2(w4.z, w4.z);
        wsd[(kc + 3) * 64 + ow] = make_float2(w4.w, w4.w);
#pragma unroll
        for (int rr = 0; rr < 4; rr++)
            xs[(xr + rr * 4) * 64 + xc] = X[(k0 + xr + rr * 4) * NDIM + n0 + xc];
        __syncthreads();
#pragma unroll
        for (int k = 0; k < 16; k++) {
            ulonglong2 a01 = *(const ulonglong2*)(wsd + k * 64 + i0);
            ulonglong2 a23 = *(const ulonglong2*)(wsd + k * 64 + i0 + 2);
            ulonglong2 xp  = *(const ulonglong2*)(xs  + k * 64 + j0);
            ffma2(acc[0][0].u, a01.x, xp.x); ffma2(acc[0][1].u, a01.x, xp.y);
            ffma2(acc[1][0].u, a01.y, xp.x); ffma2(acc[1][1].u, a01.y, xp.y);
            ffma2(acc[2][0].u, a23.x, xp.x); ffma2(acc[2][1].u, a23.x, xp.y);
            ffma2(acc[3][0].u, a23.y, xp.x); ffma2(acc[3][1].u, a23.y, xp.y);
        }
    }
#pragma unroll
    for (int ii = 0; ii < 4; ii++) {
        float bv = bias[o0 + i0 + ii];
        float4 r = make_float4(acc[ii][0].f.x + bv, acc[ii][0].f.y + bv,
                               acc[ii][1].f.x + bv, acc[ii][1].f.y + bv);
        *(float4*)(Y + (o0 + i0 + ii) * NDIM + n0 + j0) = r;
    }
}

__global__ void __launch_bounds__(256)
qkv_kernel(const float* __restrict__ x,
           const float* __restrict__ Wq, const float* __restrict__ bq,
           const float* __restrict__ Wk, const float* __restrict__ bk,
           const float* __restrict__ Wv, const float* __restrict__ bv) {
    const float* W; const float* b; float* Y;
    if (blockIdx.z == 0)      { W = Wq; b = bq; Y = g_q; }
    else if (blockIdx.z == 1) { W = Wk; b = bk; Y = g_k; }
    else                      { W = Wv; b = bv; Y = g_v; }
    gemm_tile(W, b, x, Y);
}

__global__ void __launch_bounds__(256)
proj_kernel(const float* __restrict__ Wp, const float* __restrict__ bp,
            float* __restrict__ out) {
    gemm_tile(Wp, bp, g_o, out);
}

// ---------------------------------------------------------------------------
// Fused flash attention with analytic relative-position bias.
// CTA = (head h, 64 query rows). Online softmax over 36 key tiles of 64.
// ---------------------------------------------------------------------------
#define SM_QSD 0                          // float2[32*64]  = 16384 B
#define SM_KS  16384                      // float [32*64]  =  8192 B
#define SM_VST (16384 + 8192)             // float [64*34]  =  8704 B
#define SM_PSD (16384 + 8192 + 8704)      // float2[64*66]  = 33792 B
#define SM_EMB (SM_PSD + 33792)           // float [296]    =  1184 B
#define SM_TOTAL (SM_EMB + 1184)          // 68256 B

__global__ void __launch_bounds__(256, 2)
attn_kernel(const float* __restrict__ emb) {
    extern __shared__ char smraw[];
    float2* qsd  = (float2*)(smraw + SM_QSD);
    float*  ks   = (float*) (smraw + SM_KS);
    float*  vsT  = (float*) (smraw + SM_VST);
    float2* psd  = (float2*)(smraw + SM_PSD);
    float*  embs = (float*) (smraw + SM_EMB);

    const int h   = blockIdx.y;
    const int n0  = blockIdx.x * 64;
    const int tid = threadIdx.x;
    const int ti  = tid >> 4, tj = tid & 15;
    const int i0  = ti * 4,   j0 = tj * 4;
    const int d0  = tj * 2;

    // emb table into smem; pad row (36) forced to zero
    for (int idx = tid; idx < 296; idx += 256)
        embs[idx] = (idx >= 288) ? 0.f : emb[idx];

    const float* Qh = g_q + (h * HD) * NDIM;
    const float* Kh = g_k + (h * HD) * NDIM;
    const float* Vh = g_v + (h * HD) * NDIM;

    // Q tile (32 x 64) as duplicated f32x2 pairs, resident all kernel
#pragma unroll
    for (int e = 0; e < 8; e++) {
        int idx = tid + e * 256;
        int d = idx >> 6, i = idx & 63;
        float qv = Qh[d * NDIM + n0 + i];
        qsd[d * 64 + i] = make_float2(qv, qv);
    }

    int xn[4], yn[4];
#pragma unroll
    for (int ii = 0; ii < 4; ii++) {
        int n = n0 + i0 + ii;
        xn[ii] = n / 48; yn[ii] = n - 48 * xn[ii];
    }

    U64 o2[4];
#pragma unroll
    for (int ii = 0; ii < 4; ii++) o2[ii].u = 0ull;
    float mi[4] = {-1e30f, -1e30f, -1e30f, -1e30f};
    float li[4] = {0.f, 0.f, 0.f, 0.f};
    const float scale = 0.17677669529663687f;  // 32^-0.5

    for (int m0 = 0; m0 < NDIM; m0 += 64) {
        __syncthreads();
#pragma unroll
        for (int e = 0; e < 8; e++) {
            int idx = tid + e * 256;
            int d = idx >> 6, j = idx & 63;
            ks [d * 64 + j]  = Kh[d * NDIM + m0 + j];
            vsT[j * 34 + d]  = Vh[d * NDIM + m0 + j];
        }
        __syncthreads();

        // S = Q^T K  (4x4 per thread, packed over j pairs)
        U64 s2[4][2];
#pragma unroll
        for (int a = 0; a < 4; a++) { s2[a][0].u = 0ull; s2[a][1].u = 0ull; }
#pragma unroll
        for (int d = 0; d < 32; d++) {
            ulonglong2 qa = *(const ulonglong2*)(qsd + d * 64 + i0);
            ulonglong2 qb = *(const ulonglong2*)(qsd + d * 64 + i0 + 2);
            ulonglong2 kp = *(const ulonglong2*)(ks  + d * 64 + j0);
            ffma2(s2[0][0].u, qa.x, kp.x); ffma2(s2[0][1].u, qa.x, kp.y);
            ffma2(s2[1][0].u, qa.y, kp.x); ffma2(s2[1][1].u, qa.y, kp.y);
            ffma2(s2[2][0].u, qb.x, kp.x); ffma2(s2[2][1].u, qb.x, kp.y);
            ffma2(s2[3][0].u, qb.y, kp.x); ffma2(s2[3][1].u, qb.y, kp.y);
        }

        float s[4][4];
#pragma unroll
        for (int ii = 0; ii < 4; ii++) {
            s[ii][0] = s2[ii][0].f.x; s[ii][1] = s2[ii][0].f.y;
            s[ii][2] = s2[ii][1].f.x; s[ii][3] = s2[ii][1].f.y;
        }

        // scale + analytic relative-position bias
        int xm[4], ym[4];
#pragma unroll
        for (int jj = 0; jj < 4; jj++) {
            int m = m0 + j0 + jj;
            xm[jj] = m / 48; ym[jj] = m - 48 * xm[jj];
        }
#pragma unroll
        for (int ii = 0; ii < 4; ii++)
#pragma unroll
            for (int jj = 0; jj < 4; jj++) {
                int dx = xn[ii] - xm[jj]; dx = dx < 0 ? -dx : dx;
                int dy = yn[ii] - ym[jj]; dy = dy < 0 ? -dy : dy;
                float bb = (dx < 6 && dy < 6) ? embs[(dx * 6 + dy) * 8 + h] : 0.f;
                s[ii][jj] = s[ii][jj] * scale + bb;
            }

        // online softmax (row reductions across the 16 tj lanes)
        float mx[4];
#pragma unroll
        for (int ii = 0; ii < 4; ii++)
            mx[ii] = fmaxf(fmaxf(s[ii][0], s[ii][1]), fmaxf(s[ii][2], s[ii][3]));
#pragma unroll
        for (int off = 1; off < 16; off <<= 1)
#pragma unroll
            for (int ii = 0; ii < 4; ii++)
                mx[ii] = fmaxf(mx[ii], __shfl_xor_sync(0xffffffffu, mx[ii], off));

        float rf[4], rs[4];
#pragma unroll
        for (int ii = 0; ii < 4; ii++) {
            float mn = fmaxf(mi[ii], mx[ii]);
            rf[ii] = __expf(mi[ii] - mn);
            mi[ii] = mn;
            float p0 = __expf(s[ii][0] - mn);
            float p1 = __expf(s[ii][1] - mn);
            float p2 = __expf(s[ii][2] - mn);
            float p3 = __expf(s[ii][3] - mn);
            s[ii][0] = p0; s[ii][1] = p1; s[ii][2] = p2; s[ii][3] = p3;
            rs[ii] = (p0 + p1) + (p2 + p3);
        }
#pragma unroll
        for (int off = 1; off < 16; off <<= 1)
#pragma unroll
            for (int ii = 0; ii < 4; ii++)
                rs[ii] += __shfl_xor_sync(0xffffffffu, rs[ii], off);
#pragma unroll
        for (int ii = 0; ii < 4; ii++)
            li[ii] = li[ii] * rf[ii] + rs[ii];

        // stage P (duplicated pairs, transposed [j][i]) and rescale O
#pragma unroll
        for (int jj = 0; jj < 4; jj++)
#pragma unroll
            for (int ii = 0; ii < 4; ii++)
                psd[(j0 + jj) * 66 + i0 + ii] = make_float2(s[ii][jj], s[ii][jj]);
#pragma unroll
        for (int ii = 0; ii < 4; ii++) {
            o2[ii].f.x *= rf[ii];
            o2[ii].f.y *= rf[ii];
        }
        __syncthreads();

        // O[i][d0,d0+1] += sum_j P[i][j] * V[d][j]
#pragma unroll 8
        for (int j = 0; j < 64; j++) {
            ulonglong2 pa = *(const ulonglong2*)(psd + j * 66 + i0);
            ulonglong2 pb = *(const ulonglong2*)(psd + j * 66 + i0 + 2);
            unsigned long long vp = *(const unsigned long long*)(vsT + j * 34 + d0);
            ffma2(o2[0].u, pa.x, vp);
            ffma2(o2[1].u, pa.y, vp);
            ffma2(o2[2].u, pb.x, vp);
            ffma2(o2[3].u, pb.y, vp);
        }
    }

    float* Oh = g_o + (h * HD) * NDIM;
#pragma unroll
    for (int ii = 0; ii < 4; ii++) {
        float invl = 1.0f / li[ii];
        int n = n0 + i0 + ii;
        Oh[(d0 + 0) * NDIM + n] = o2[ii].f.x * invl;
        Oh[(d0 + 1) * NDIM + n] = o2[ii].f.y * invl;
    }
}

// ---------------------------------------------------------------------------
extern "C" void kernel_launch(void* const* d_in, const int* in_sizes, int n_in,
                              void* d_out, int out_size) {
    const float* x   = (const float*)d_in[0];
    const float* Wq  = (const float*)d_in[1];
    const float* bq  = (const float*)d_in[2];
    const float* Wk  = (const float*)d_in[3];
    const float* bk  = (const float*)d_in[4];
    const float* Wv  = (const float*)d_in[5];
    const float* bv  = (const float*)d_in[6];
    const float* Wp  = (const float*)d_in[7];
    const float* bp  = (const float*)d_in[8];
    const float* emb = (const float*)d_in[9];
    // d_in[10] = tokens (int32) — recomputed analytically in-kernel, unused
    float* out = (float*)d_out;

    cudaFuncSetAttribute(attn_kernel,
                         cudaFuncAttributeMaxDynamicSharedMemorySize, SM_TOTAL);

    qkv_kernel<<<dim3(36, 4, 3), 256>>>(x, Wq, bq, Wk, bk, Wv, bv);
    attn_kernel<<<dim3(36, HEADS), 256, SM_TOTAL>>>(emb);
    proj_kernel<<<dim3(36, 4), 256>>>(Wp, bp, out);
}

// round 5
// speedup vs baseline: 2.9666x; 2.9666x over previous
#include <cuda_runtime.h>
#include <cuda_bf16.h>
#include <cuda_fp16.h>
#define NDIM 2304
#define HEADS 8

__device__ __align__(16) __nv_bfloat16 g_qp[HEADS*NDIM*64];
__device__ __align__(16) __nv_bfloat16 g_kp[HEADS*NDIM*64];
__device__ __align__(16) __half g_vh[256*NDIM];
__device__ __align__(16) float g_q[256*NDIM];
__device__ __align__(16) float g_k[256*NDIM];
__device__ __align__(16) float g_v[256*NDIM];
__device__ __align__(16) float g_o[256*NDIM];

union U64{unsigned long long u; float2 f;};
__device__ __forceinline__ void ffma2(unsigned long long&a,unsigned long long b,unsigned long long c){
    asm("fma.rn.f32x2 %0, %1, %2, %0;":"+l"(a):"l"(b),"l"(c));}

#if defined(__CUDA_ARCH_FEAT_SM103_ALL) || defined(__CUDA_ARCH_FEAT_SM100_ALL)
#define HAS_TC 1
#endif

__device__ __forceinline__ unsigned su32(const void*p){unsigned a;
    asm("{.reg .u64 t; cvta.to.shared.u64 t,%1; cvt.u32.u64 %0,t;}":"=r"(a):"l"(p));return a;}
#define TC_ALLOC(sa,n) asm volatile("tcgen05.alloc.cta_group::1.sync.aligned.shared::cta.b32 [%0],%1;"::"r"(sa),"r"(n):"memory")
#define TC_DEALLOC(t,n) asm volatile("tcgen05.dealloc.cta_group::1.sync.aligned.b32 %0,%1;"::"r"(t),"r"(n))
#define TC_COMMIT(mb) asm volatile("tcgen05.commit.cta_group::1.mbarrier::arrive::one.shared::cluster.b64 [%0];"::"r"(mb):"memory")
#define TC_FA() asm volatile("tcgen05.fence::after_thread_sync;":::"memory")
#define TC_FB() asm volatile("tcgen05.fence::before_thread_sync;":::"memory")
#define TC_WLD() asm volatile("tcgen05.wait::ld.sync.aligned;":::"memory")
#define TC_WST() asm volatile("tcgen05.wait::st.sync.aligned;":::"memory")
#define FPA() asm volatile("fence.proxy.async.shared::cta;":::"memory")
#define MBI(mb,c) asm volatile("mbarrier.init.shared.b64 [%0],%1;"::"r"(mb),"r"(c):"memory")
#define MBW(mb,ph) do{unsigned _d=0;while(!_d){asm volatile("{.reg .pred p;\n mbarrier.try_wait.parity.acquire.cta.shared::cta.b64 p,[%1],%2;\n selp.b32 %0,1,0,p;}":"=r"(_d):"r"(mb),"r"(ph):"memory");}}while(0)
#define TC_LD32(r,a) asm volatile("tcgen05.ld.sync.aligned.32x32b.x32.b32 {%0,%1,%2,%3,%4,%5,%6,%7,%8,%9,%10,%11,%12,%13,%14,%15,%16,%17,%18,%19,%20,%21,%22,%23,%24,%25,%26,%27,%28,%29,%30,%31},[%32];" \
 :"=r"((r)[0]),"=r"((r)[1]),"=r"((r)[2]),"=r"((r)[3]),"=r"((r)[4]),"=r"((r)[5]),"=r"((r)[6]),"=r"((r)[7]),"=r"((r)[8]),"=r"((r)[9]),"=r"((r)[10]),"=r"((r)[11]),"=r"((r)[12]),"=r"((r)[13]),"=r"((r)[14]),"=r"((r)[15]), \
  "=r"((r)[16]),"=r"((r)[17]),"=r"((r)[18]),"=r"((r)[19]),"=r"((r)[20]),"=r"((r)[21]),"=r"((r)[22]),"=r"((r)[23]),"=r"((r)[24]),"=r"((r)[25]),"=r"((r)[26]),"=r"((r)[27]),"=r"((r)[28]),"=r"((r)[29]),"=r"((r)[30]),"=r"((r)[31]):"r"(a))
#define TC_LD1(r0,a) asm volatile("tcgen05.ld.sync.aligned.32x32b.x1.b32 {%0},[%1];":"=r"(r0):"r"(a))
#define TC_ST16(a,r) asm volatile("tcgen05.st.sync.aligned.32x32b.x16.b32 [%0],{%1,%2,%3,%4,%5,%6,%7,%8,%9,%10,%11,%12,%13,%14,%15,%16};" \
 ::"r"(a),"r"((r)[0]),"r"((r)[1]),"r"((r)[2]),"r"((r)[3]),"r"((r)[4]),"r"((r)[5]),"r"((r)[6]),"r"((r)[7]),"r"((r)[8]),"r"((r)[9]),"r"((r)[10]),"r"((r)[11]),"r"((r)[12]),"r"((r)[13]),"r"((r)[14]),"r"((r)[15]):"memory")
#define SWZ(x) ((x)^(((x)>>3)&0x70))
__device__ __forceinline__ unsigned long long mkd(unsigned a){
    return ((2ull<<61)|(1ull<<46)|(64ull<<32)|(1ull<<16))|((unsigned long long)(a>>4)&0x3FFF);}
__device__ __forceinline__ void mma_ss(unsigned d,unsigned long long a,unsigned long long b,unsigned id,unsigned en){
    asm volatile("{.reg .pred p;\n setp.ne.u32 p,%5,0;\n tcgen05.mma.cta_group::1.kind::f16 [%0],%1,%2,%3,{%4,%4,%4,%4},p;}"
    ::"r"(d),"l"(a),"l"(b),"r"(id),"r"(0u),"r"(en):"memory");}
__device__ __forceinline__ void mma_ts(unsigned d,unsigned a,unsigned long long b,unsigned id,unsigned en){
    asm volatile("{.reg .pred p;\n setp.ne.u32 p,%5,0;\n tcgen05.mma.cta_group::1.kind::f16 [%0],[%1],%2,%3,{%4,%4,%4,%4},p;}"
    ::"r"(d),"r"(a),"l"(b),"r"(id),"r"(0u),"r"(en):"memory");}
__device__ __forceinline__ float ex2f(float x){float y;asm("ex2.approx.ftz.f32 %0,%1;":"=f"(y):"f"(x));return y;}
__device__ __forceinline__ unsigned f16p(float lo,float hi){unsigned r;
    asm("cvt.rn.f16x2.f32 %0,%1,%2;":"=r"(r):"f"(hi),"f"(lo));return r;}
#define IDS 0x8100490u
#define IDP 0x80A0010u

// ------------------- QKV gemm (FFMA2); epilogue writes fp32 + packed -------------------
__global__ void __launch_bounds__(256)
qkv_kernel(const float* __restrict__ x,const float* __restrict__ Wq,const float* __restrict__ bq,
           const float* __restrict__ Wk,const float* __restrict__ bk,
           const float* __restrict__ Wv,const float* __restrict__ bv){
    __shared__ float2 wsd[16*64]; __shared__ float xs[16*64];
    const int z=blockIdx.z;
    const float* W=(z==0)?Wq:(z==1)?Wk:Wv; const float* bb=(z==0)?bq:(z==1)?bk:bv;
    const int tid=threadIdx.x,n0=blockIdx.x*64,o0=blockIdx.y*64;
    const int i0=(tid>>4)*4,j0=(tid&15)*4,ow=tid>>2,kc=(tid&3)*4,xr=tid>>6,xc=tid&63;
    U64 acc[4][2];
#pragma unroll
    for(int a=0;a<4;a++){acc[a][0].u=0;acc[a][1].u=0;}
    for(int k0=0;k0<256;k0+=16){
        __syncthreads();
        float4 w4=*(const float4*)(W+(o0+ow)*256+k0+kc);
        wsd[(kc+0)*64+ow]=make_float2(w4.x,w4.x); wsd[(kc+1)*64+ow]=make_float2(w4.y,w4.y);
        wsd[(kc+2)*64+ow]=make_float2(w4.z,w4.z); wsd[(kc+3)*64+ow]=make_float2(w4.w,w4.w);
#pragma unroll
        for(int rr=0;rr<4;rr++) xs[(xr+rr*4)*64+xc]=x[(k0+xr+rr*4)*NDIM+n0+xc];
        __syncthreads();
#pragma unroll
        for(int k=0;k<16;k++){
            ulonglong2 a01=*(const ulonglong2*)(wsd+k*64+i0);
            ulonglong2 a23=*(const ulonglong2*)(wsd+k*64+i0+2);
            ulonglong2 xp =*(const ulonglong2*)(xs +k*64+j0);
            ffma2(acc[0][0].u,a01.x,xp.x); ffma2(acc[0][1].u,a01.x,xp.y);
            ffma2(acc[1][0].u,a01.y,xp.x); ffma2(acc[1][1].u,a01.y,xp.y);
            ffma2(acc[2][0].u,a23.x,xp.x); ffma2(acc[2][1].u,a23.x,xp.y);
            ffma2(acc[3][0].u,a23.y,xp.x); ffma2(acc[3][1].u,a23.y,xp.y);
        }
    }
    const float CQ=0.17677669529663687f*1.4426950408889634f;
#pragma unroll
    for(int ii=0;ii<4;ii++){
        int o=o0+i0+ii; float bv_=bb[o];
        float v[4]={acc[ii][0].f.x+bv_,acc[ii][0].f.y+bv_,acc[ii][1].f.x+bv_,acc[ii][1].f.y+bv_};
        float* f32dst=((z==0)?g_q:(z==1)?g_k:g_v)+o*NDIM+n0+j0;
        *(float4*)f32dst=make_float4(v[0],v[1],v[2],v[3]);
        if(z==2){
            __half* d=g_vh+o*NDIM+n0+j0;
#pragma unroll
            for(int jj=0;jj<4;jj++) d[jj]=__float2half(v[jj]);
        }else{
            float c=(z==0)?CQ:1.f;
            __nv_bfloat16* d=((z==0)?g_qp:g_kp)+(o>>5)*(NDIM*64);
            int dd=o&31;
#pragma unroll
            for(int jj=0;jj<4;jj++){
                float vv=v[jj]*c; int n=n0+j0+jj;
                __nv_bfloat16 hi=__float2bfloat16(vv);
                d[n*64+dd]=hi; d[n*64+32+dd]=__float2bfloat16(vv-__bfloat162float(hi));
            }
        }
    }
}

__global__ void __launch_bounds__(256)
proj_kernel(const float* __restrict__ Wp,const float* __restrict__ bp,float* __restrict__ out){
    __shared__ float2 wsd[16*64]; __shared__ float xs[16*64];
    const int tid=threadIdx.x,n0=blockIdx.x*64,o0=blockIdx.y*64;
    const int i0=(tid>>4)*4,j0=(tid&15)*4,ow=tid>>2,kc=(tid&3)*4,xr=tid>>6,xc=tid&63;
    U64 acc[4][2];
#pragma unroll
    for(int a=0;a<4;a++){acc[a][0].u=0;acc[a][1].u=0;}
    for(int k0=0;k0<256;k0+=16){
        __syncthreads();
        float4 w4=*(const float4*)(Wp+(o0+ow)*256+k0+kc);
        wsd[(kc+0)*64+ow]=make_float2(w4.x,w4.x); wsd[(kc+1)*64+ow]=make_float2(w4.y,w4.y);
        wsd[(kc+2)*64+ow]=make_float2(w4.z,w4.z); wsd[(kc+3)*64+ow]=make_float2(w4.w,w4.w);
#pragma unroll
        for(int rr=0;rr<4;rr++) xs[(xr+rr*4)*64+xc]=g_o[(k0+xr+rr*4)*NDIM+n0+xc];
        __syncthreads();
#pragma unroll
        for(int k=0;k<16;k++){
            ulonglong2 a01=*(const ulonglong2*)(wsd+k*64+i0);
            ulonglong2 a23=*(const ulonglong2*)(wsd+k*64+i0+2);
            ulonglong2 xp =*(const ulonglong2*)(xs +k*64+j0);
            ffma2(acc[0][0].u,a01.x,xp.x); ffma2(acc[0][1].u,a01.x,xp.y);
            ffma2(acc[1][0].u,a01.y,xp.x); ffma2(acc[1][1].u,a01.y,xp.y);
            ffma2(acc[2][0].u,a23.x,xp.x); ffma2(acc[2][1].u,a23.x,xp.y);
            ffma2(acc[3][0].u,a23.y,xp.x); ffma2(acc[3][1].u,a23.y,xp.y);
        }
    }
#pragma unroll
    for(int ii=0;ii<4;ii++){
        float bv=bp[o0+i0+ii];
        *(float4*)(out+(o0+i0+ii)*NDIM+n0+j0)=make_float4(acc[ii][0].f.x+bv,acc[ii][0].f.y+bv,acc[ii][1].f.x+bv,acc[ii][1].f.y+bv);
    }
}

// ------------------- attention: tcgen05 fast path + FFMA fallback -------------------
#define SM_B 64
#define SM_Q 36864
#define SM_K0 53248
#define SM_K1 61440
#define SM_V0 69632
#define SM_V1 74752
#define SM_TOT 79872

#ifdef HAS_TC
__device__ __forceinline__ void load_kv(char* sm,int ko,int vo,int m0,int H,int tid,
                                        const __nv_bfloat16* kp){
#pragma unroll
    for(int e=0;e<2;e++){
        int idx=tid+e*256,j=idx>>3,c=(idx&7)*16;
        uint4 v=*(const uint4*)((const char*)(kp+(m0+j)*64)+c);
        *(uint4*)(sm+ko+SWZ(j*128+c))=v;
    }
    int d=tid>>3,c=(tid&7)*16;
    uint4 v=*(const uint4*)((const char*)(g_vh+(H*32+d)*NDIM+m0)+c);
    *(uint4*)(sm+vo+SWZ(d*128+c))=v;
}
#endif

__global__ void __launch_bounds__(256,1)
attn_kernel(const float* __restrict__ emb){
    extern __shared__ char sm[];
#ifdef HAS_TC
    const unsigned smb=su32(sm);
    const int tid=threadIdx.x,wid=tid>>5,lid=tid&31;
    const int H=blockIdx.y,n0=blockIdx.x*128;
    float* bias=(float*)(sm+SM_B);
    if(wid==0) TC_ALLOC(smb,512);
    if(tid==0){MBI(smb+8,1);MBI(smb+16,1);}
    for(int i=tid;i<9025;i+=256){
        int a=i/95,b=i-a*95,dx=a-47,dy=b-47;
        if(dx<0)dx=-dx; if(dy<0)dy=-dy;
        bias[i]=(dx<=5&&dy<=5)?emb[(dx*6+dy)*8+H]*1.4426950408889634f:0.f;
    }
    const __nv_bfloat16* qp=g_qp+H*(NDIM*64);
    const __nv_bfloat16* kp=g_kp+H*(NDIM*64);
#pragma unroll
    for(int e=0;e<4;e++){
        int idx=tid+e*256,r=idx>>3,c=(idx&7)*16;
        uint4 v=*(const uint4*)((const char*)(qp+(n0+r)*64)+c);
        *(uint4*)(sm+SM_Q+SWZ(r*128+c))=v;
    }
    if(tid<64){
        int d=32+(tid>>3),c=(tid&7)*16;
        unsigned w=(d==32)?0x3C003C00u:0u; uint4 z=make_uint4(w,w,w,w);
        *(uint4*)(sm+SM_V0+SWZ(d*128+c))=z; *(uint4*)(sm+SM_V1+SWZ(d*128+c))=z;
    }
    load_kv(sm,SM_K0,SM_V0,0,H,tid,kp);
    FPA(); __syncthreads();
    unsigned tmem; asm volatile("ld.shared.b32 %0,[%1];":"=r"(tmem):"r"(smb));
    const int sp=wid&3,hf=wid>>2;
    const unsigned spoff=(unsigned)sp<<21;
    const int n=n0+sp*32+lid,xn=n/48,yn=n-xn*48;
    const float* bp=bias+xn*95+yn+4512;
    const unsigned long long qd=mkd(smb+SM_Q);

    for(int t=0;t<36;t++){
        const int buf=t&1;
        if(tid==0){
            unsigned long long kd=mkd(smb+(buf?SM_K1:SM_K0));
            unsigned tS=tmem+64;
            mma_ss(tS,qd+0,kd+0,IDS,0); mma_ss(tS,qd+2,kd+2,IDS,1);
            mma_ss(tS,qd+0,kd+4,IDS,1); mma_ss(tS,qd+2,kd+6,IDS,1);
            mma_ss(tS,qd+4,kd+0,IDS,1); mma_ss(tS,qd+6,kd+2,IDS,1);
            TC_COMMIT(smb+8);
        }
        if(t>0) MBW(smb+16,(t-1)&1);          // PV(t-1) done: P and V[1-buf] free
        if(t<35) load_kv(sm,buf?SM_K0:SM_K1,buf?SM_V0:SM_V1,(t+1)*64,H,tid,kp);
        FPA();
        MBW(smb+8,t&1); TC_FA();
        unsigned sr[32];
        TC_LD32(sr,tmem+64+hf*32+spoff); TC_WLD();
        const int mc=t*64+hf*32;
        unsigned pk[16];
#pragma unroll
        for(int jj=0;jj<16;jj++){
            int m0_=mc+2*jj,m1_=m0_+1;
            int x0=(m0_*2731)>>17,x1=(m1_*2731)>>17;
            float p0=ex2f(__uint_as_float(sr[2*jj])+bp[-(m0_+47*x0)]);
            float p1=ex2f(__uint_as_float(sr[2*jj+1])+bp[-(m1_+47*x1)]);
            pk[jj]=f16p(p0,p1);
        }
        TC_ST16(tmem+128+hf*16+spoff,pk); TC_WST();
        TC_FB(); __syncthreads();
        if(tid==0){
            TC_FA();
            unsigned long long vd=mkd(smb+(buf?SM_V1:SM_V0));
#pragma unroll
            for(int k=0;k<4;k++) mma_ts(tmem,tmem+128+k*8,vd+k*2,IDP,(t+k)>0);
            TC_COMMIT(smb+16);
        }
        __syncthreads();
    }
    MBW(smb+16,1); TC_FA();
    if(hf==0){
        unsigned od[32],lr;
        TC_LD32(od,tmem+spoff); TC_LD1(lr,tmem+32+spoff); TC_WLD();
        float invl=1.f/__uint_as_float(lr);
#pragma unroll
        for(int d=0;d<32;d++) g_o[(H*32+d)*NDIM+n]=__uint_as_float(od[d])*invl;
    }
    __syncthreads();
    if(wid==0) TC_DEALLOC(tmem,512);
#else
    // -------- FFMA fallback (R1 algorithm, 2 x 64-query halves) --------
    float2* qsd=(float2*)sm; float* ks=(float*)(sm+16384); float* vsT=(float*)(sm+24576);
    float2* psd=(float2*)(sm+33280); float* embs=(float*)(sm+67072);
    const int h=blockIdx.y,tid=threadIdx.x,ti=tid>>4,tj=tid&15;
    const int i0=ti*4,j0=tj*4,d0=tj*2;
    for(int idx=tid;idx<296;idx+=256) embs[idx]=(idx>=288)?0.f:emb[idx];
    const float* Qh=g_q+(h*32)*NDIM; const float* Kh=g_k+(h*32)*NDIM; const float* Vh=g_v+(h*32)*NDIM;
    for(int half=0;half<2;half++){
        const int n0=blockIdx.x*128+half*64;
#pragma unroll
        for(int e=0;e<8;e++){
            int idx=tid+e*256,d=idx>>6,i=idx&63;
            float qv=Qh[d*NDIM+n0+i]; qsd[d*64+i]=make_float2(qv,qv);
        }
        int xn[4],yn[4];
#pragma unroll
        for(int ii=0;ii<4;ii++){int n=n0+i0+ii; xn[ii]=n/48; yn[ii]=n-48*xn[ii];}
        U64 o2[4];
#pragma unroll
        for(int ii=0;ii<4;ii++) o2[ii].u=0;
        float mi[4]={-1e30f,-1e30f,-1e30f,-1e30f},li[4]={0,0,0,0};
        const float scale=0.17677669529663687f;
        for(int m0=0;m0<NDIM;m0+=64){
            __syncthreads();
#pragma unroll
            for(int e=0;e<8;e++){
                int idx=tid+e*256,d=idx>>6,j=idx&63;
                ks[d*64+j]=Kh[d*NDIM+m0+j]; vsT[j*34+d]=Vh[d*NDIM+m0+j];
            }
            __syncthreads();
            U64 s2[4][2];
#pragma unroll
            for(int a=0;a<4;a++){s2[a][0].u=0;s2[a][1].u=0;}
#pragma unroll
            for(int d=0;d<32;d++){
                ulonglong2 qa=*(const ulonglong2*)(qsd+d*64+i0);
                ulonglong2 qb=*(const ulonglong2*)(qsd+d*64+i0+2);
                ulonglong2 kq=*(const ulonglong2*)(ks+d*64+j0);
                ffma2(s2[0][0].u,qa.x,kq.x); ffma2(s2[0][1].u,qa.x,kq.y);
                ffma2(s2[1][0].u,qa.y,kq.x); ffma2(s2[1][1].u,qa.y,kq.y);
                ffma2(s2[2][0].u,qb.x,kq.x); ffma2(s2[2][1].u,qb.x,kq.y);
                ffma2(s2[3][0].u,qb.y,kq.x); ffma2(s2[3][1].u,qb.y,kq.y);
            }
            float s[4][4];
#pragma unroll
            for(int ii=0;ii<4;ii++){s[ii][0]=s2[ii][0].f.x;s[ii][1]=s2[ii][0].f.y;s[ii][2]=s2[ii][1].f.x;s[ii][3]=s2[ii][1].f.y;}
            int xm[4],ym[4];
#pragma unroll
            for(int jj=0;jj<4;jj++){int m=m0+j0+jj; xm[jj]=m/48; ym[jj]=m-48*xm[jj];}
#pragma unroll
            for(int ii=0;ii<4;ii++)
#pragma unroll
                for(int jj=0;jj<4;jj++){
                    int dx=xn[ii]-xm[jj]; dx=dx<0?-dx:dx;
                    int dy=yn[ii]-ym[jj]; dy=dy<0?-dy:dy;
                    float bb=(dx<6&&dy<6)?embs[(dx*6+dy)*8+h]:0.f;
                    s[ii][jj]=s[ii][jj]*scale+bb;
                }
            float mx[4];
#pragma unroll
            for(int ii=0;ii<4;ii++) mx[ii]=fmaxf(fmaxf(s[ii][0],s[ii][1]),fmaxf(s[ii][2],s[ii][3]));
#pragma unroll
            for(int off=1;off<16;off<<=1)
#pragma unroll
                for(int ii=0;ii<4;ii++) mx[ii]=fmaxf(mx[ii],__shfl_xor_sync(0xffffffffu,mx[ii],off));
            float rf[4],rs[4];
#pragma unroll
            for(int ii=0;ii<4;ii++){
                float mn=fmaxf(mi[ii],mx[ii]); rf[ii]=__expf(mi[ii]-mn); mi[ii]=mn;
                float p0=__expf(s[ii][0]-mn),p1=__expf(s[ii][1]-mn),p2=__expf(s[ii][2]-mn),p3=__expf(s[ii][3]-mn);
                s[ii][0]=p0;s[ii][1]=p1;s[ii][2]=p2;s[ii][3]=p3; rs[ii]=(p0+p1)+(p2+p3);
            }
#pragma unroll
            for(int off=1;off<16;off<<=1)
#pragma unroll
                for(int ii=0;ii<4;ii++) rs[ii]+=__shfl_xor_sync(0xffffffffu,rs[ii],off);
#pragma unroll
            for(int ii=0;ii<4;ii++) li[ii]=li[ii]*rf[ii]+rs[ii];
#pragma unroll
            for(int jj=0;jj<4;jj++)
#pragma unroll
                for(int ii=0;ii<4;ii++) psd[(j0+jj)*66+i0+ii]=make_float2(s[ii][jj],s[ii][jj]);
#pragma unroll
            for(int ii=0;ii<4;ii++){o2[ii].f.x*=rf[ii];o2[ii].f.y*=rf[ii];}
            __syncthreads();
#pragma unroll 8
            for(int j=0;j<64;j++){
                ulonglong2 pa=*(const ulonglong2*)(psd+j*66+i0);
                ulonglong2 pb=*(const ulonglong2*)(psd+j*66+i0+2);
                unsigned long long vp=*(const unsigned long long*)(vsT+j*34+d0);
                ffma2(o2[0].u,pa.x,vp); ffma2(o2[1].u,pa.y,vp);
                ffma2(o2[2].u,pb.x,vp); ffma2(o2[3].u,pb.y,vp);
            }
        }
        float* Oh=g_o+(h*32)*NDIM;
#pragma unroll
        for(int ii=0;ii<4;ii++){
            float invl=1.0f/li[ii]; int n=n0+i0+ii;
            Oh[(d0+0)*NDIM+n]=o2[ii].f.x*invl; Oh[(d0+1)*NDIM+n]=o2[ii].f.y*invl;
        }
        __syncthreads();
    }
#endif
}

extern "C" void kernel_launch(void* const* d_in,const int* in_sizes,int n_in,
                              void* d_out,int out_size){
    const float* x  =(const float*)d_in[0];
    const float* Wq =(const float*)d_in[1]; const float* bq=(const float*)d_in[2];
    const float* Wk =(const float*)d_in[3]; const float* bk=(const float*)d_in[4];
    const float* Wv =(const float*)d_in[5]; const float* bv=(const float*)d_in[6];
    const float* Wp =(const float*)d_in[7]; const float* bp=(const float*)d_in[8];
    const float* emb=(const float*)d_in[9];
    float* out=(float*)d_out;
    cudaFuncSetAttribute(attn_kernel,cudaFuncAttributeMaxDynamicSharedMemorySize,SM_TOT);
    qkv_kernel<<<dim3(36,4,3),256>>>(x,Wq,bq,Wk,bk,Wv,bv);
    attn_kernel<<<dim3(18,HEADS),256,SM_TOT>>>(emb);
    proj_kernel<<<dim3(36,4),256>>>(Wp,bp,out);
}